// round 6
// baseline (speedup 1.0000x reference)
#include <cuda_runtime.h>
#include <cstdint>

#define NUM_NODES 50000
#define INPUT_SIZE 128
#define NUM_REL 16
#define NUM_EDGES 1600000
#define CLAMP_MIN 1e-5f
#define CLAMP_MAX 0.99999f

// Node logit table: T[n][0:16] = x[n].W_src, T[n][16:32] = x[n].W_dst
__device__ float g_table[NUM_NODES * 32];

// Packed f32x2 helpers (Blackwell FFMA2 — PTX-only).
__device__ __forceinline__ uint64_t pack2(float lo, float hi) {
    uint64_t r;
    asm("mov.b64 %0, {%1, %2};" : "=l"(r) : "f"(lo), "f"(hi));
    return r;
}
__device__ __forceinline__ void fma2(uint64_t& acc, uint64_t a, uint64_t b) {
    asm("fma.rn.f32x2 %0, %1, %2, %0;" : "+l"(acc) : "l"(a), "l"(b));
}
__device__ __forceinline__ float2 unpack2(uint64_t v) {
    float lo, hi;
    asm("mov.b64 {%0, %1}, %2;" : "=f"(lo), "=f"(hi) : "l"(v));
    return make_float2(lo, hi);
}

// ---------------------------------------------------------------------------
// Kernel A: 50000x128 @ 128x32 GEMM into g_table.
// 256 threads/block, tile 256 nodes x 32 cols, 16-k chunks (8 chunks).
// Per thread: 8 nodes x 4 cols as 4 node-pairs x 4 cols in FFMA2.
// smem 32.6KB -> 6 blocks/SM: cross-block overlap hides load phases.
// ---------------------------------------------------------------------------
#define XPAD 260

__global__ void __launch_bounds__(256) node_logits_kernel(
    const float* __restrict__ x, const float* __restrict__ W)
{
    __shared__ float Ws[INPUT_SIZE][32];   // 16 KB [k][r]
    __shared__ float Xs[16][XPAD];         // 16.6 KB [k-within-chunk][node]

    const int tid = threadIdx.x;

    for (int idx = tid; idx < INPUT_SIZE * 32; idx += 256) {
        int k = idx >> 5;
        int r = idx & 31;
        Ws[k][r] = (r < NUM_REL) ? W[k * NUM_REL + r]
                                 : W[(k + INPUT_SIZE) * NUM_REL + (r - NUM_REL)];
    }

    const int node0 = blockIdx.x * 256;
    const int rg = tid & 7;    // 8 groups of 4 rel-cols
    const int ng = tid >> 3;   // 32 groups of 8 nodes

    uint64_t acc2[4][4];       // [node-pair][col]
#pragma unroll
    for (int i = 0; i < 4; ++i)
#pragma unroll
        for (int j = 0; j < 4; ++j) acc2[i][j] = 0ull;

    for (int kc = 0; kc < 8; ++kc) {           // 8 chunks of 16 k
        __syncthreads();
#pragma unroll
        for (int it = 0; it < 4; ++it) {
            int s = tid + it * 256;            // 0..1023
            int row = s >> 2;                  // node within tile 0..255
            int c4  = s & 3;                   // float4 within 16-float chunk
            int gr = node0 + row;
            if (gr >= NUM_NODES) gr = NUM_NODES - 1;   // dup loads OK
            float4 v = *reinterpret_cast<const float4*>(
                &x[(size_t)gr * INPUT_SIZE + kc * 16 + c4 * 4]);
            Xs[c4 * 4 + 0][row] = v.x;
            Xs[c4 * 4 + 1][row] = v.y;
            Xs[c4 * 4 + 2][row] = v.z;
            Xs[c4 * 4 + 3][row] = v.w;
        }
        __syncthreads();

#pragma unroll
        for (int kk = 0; kk < 16; ++kk) {
            int k = kc * 16 + kk;
            float4 wv = *reinterpret_cast<const float4*>(&Ws[k][rg * 4]);
            uint64_t wd[4] = { pack2(wv.x, wv.x), pack2(wv.y, wv.y),
                               pack2(wv.z, wv.z), pack2(wv.w, wv.w) };
            float4 xa = *reinterpret_cast<const float4*>(&Xs[kk][ng * 8]);
            float4 xb = *reinterpret_cast<const float4*>(&Xs[kk][ng * 8 + 4]);
            uint64_t xp[4] = { pack2(xa.x, xa.y), pack2(xa.z, xa.w),
                               pack2(xb.x, xb.y), pack2(xb.z, xb.w) };
#pragma unroll
            for (int i = 0; i < 4; ++i)
#pragma unroll
                for (int j = 0; j < 4; ++j)
                    fma2(acc2[i][j], xp[i], wd[j]);
        }
    }

#pragma unroll
    for (int i = 0; i < 4; ++i) {
        float2 c0 = unpack2(acc2[i][0]);
        float2 c1 = unpack2(acc2[i][1]);
        float2 c2 = unpack2(acc2[i][2]);
        float2 c3 = unpack2(acc2[i][3]);
        int n0 = node0 + ng * 8 + 2 * i;
        if (n0 < NUM_NODES)
            *reinterpret_cast<float4*>(&g_table[(size_t)n0 * 32 + rg * 4]) =
                make_float4(c0.x, c1.x, c2.x, c3.x);
        if (n0 + 1 < NUM_NODES)
            *reinterpret_cast<float4*>(&g_table[(size_t)(n0 + 1) * 32 + rg * 4]) =
                make_float4(c0.y, c1.y, c2.y, c3.y);
    }
}

// ---------------------------------------------------------------------------
// FMA/ALU-only clamped sigmoid: zero MUFU, zero F2I.
// Clamp v to +-15 first: sigmoid(-15)=3e-7 < 1e-5 and sigmoid(15) > 0.99999,
// so the output clamps make this exact. Then e^{-v} = 2^n * poly(f) with
// magic-constant rounding, and 1/(1+e) via bit-trick seed + 3 Newton steps.
// ---------------------------------------------------------------------------
__device__ __forceinline__ float sigmoid_clamped(float v)
{
    v = fminf(fmaxf(v, -15.0f), 15.0f);
    float y = v * -1.4426950408889634f;            // log2(e^{-v}), |y| <= 21.7
    float z = y + 12582912.0f;                     // round to nearest int
    int   n = __float_as_int(z) - 0x4B400000;
    float f = y - (z - 12582912.0f);               // f in [-0.5, 0.5]
    float p = 0.0013333558f;                       // 2^f, deg-5, ~2e-6 rel
    p = fmaf(p, f, 0.0096181291f);
    p = fmaf(p, f, 0.0555041086f);
    p = fmaf(p, f, 0.2402265069f);
    p = fmaf(p, f, 0.6931471806f);
    p = fmaf(p, f, 1.0f);
    float e = p * __int_as_float((n + 127) << 23); // e^{-v}, n in [-22,22]
    float d = 1.0f + e;                            // d in [1, 2.7e9]
    float r = __int_as_float(0x7EF311C3 - __float_as_int(d));
    r = r * (2.0f - d * r);
    r = r * (2.0f - d * r);
    r = r * (2.0f - d * r);
    return fminf(fmaxf(r, CLAMP_MIN), CLAMP_MAX);
}

// ---------------------------------------------------------------------------
// Kernel B: per-edge gather + sigmoid + clamp.
// 4 edges/thread, 256-thr blocks (measured-best occupancy/latency config).
// ---------------------------------------------------------------------------
__global__ void __launch_bounds__(256) edge_kernel(
    const int* __restrict__ ei,
    const int* __restrict__ et,
    float* __restrict__ out)
{
    const int q = blockIdx.x * 256 + threadIdx.x;
    const int e0 = q * 4;
    if (e0 + 3 < NUM_EDGES) {
        int4 s4 = *reinterpret_cast<const int4*>(ei + e0);
        int4 d4 = *reinterpret_cast<const int4*>(ei + NUM_EDGES + e0);
        int4 t4 = *reinterpret_cast<const int4*>(et + e0);

        float a0 = __ldg(&g_table[s4.x * 32 + t4.x]);
        float a1 = __ldg(&g_table[s4.y * 32 + t4.y]);
        float a2 = __ldg(&g_table[s4.z * 32 + t4.z]);
        float a3 = __ldg(&g_table[s4.w * 32 + t4.w]);
        float b0 = __ldg(&g_table[d4.x * 32 + 16 + t4.x]);
        float b1 = __ldg(&g_table[d4.y * 32 + 16 + t4.y]);
        float b2 = __ldg(&g_table[d4.z * 32 + 16 + t4.z]);
        float b3 = __ldg(&g_table[d4.w * 32 + 16 + t4.w]);

        float4 o;
        o.x = sigmoid_clamped(a0 + b0);
        o.y = sigmoid_clamped(a1 + b1);
        o.z = sigmoid_clamped(a2 + b2);
        o.w = sigmoid_clamped(a3 + b3);
        *reinterpret_cast<float4*>(out + e0) = o;
    } else {
        for (int e = e0; e < NUM_EDGES; ++e) {
            int s = ei[e], d = ei[NUM_EDGES + e], t = et[e];
            out[e] = sigmoid_clamped(g_table[s * 32 + t] + g_table[d * 32 + 16 + t]);
        }
    }
}

extern "C" void kernel_launch(void* const* d_in, const int* in_sizes, int n_in,
                              void* d_out, int out_size)
{
    const float* x  = (const float*)d_in[0];
    const float* W  = (const float*)d_in[1];
    const int*   ei = (const int*)d_in[2];
    const int*   et = (const int*)d_in[3];
    float* out = (float*)d_out;

    const int node_blocks = (NUM_NODES + 255) / 256;     // 196
    node_logits_kernel<<<node_blocks, 256>>>(x, W);

    const int quads = (NUM_EDGES + 3) / 4;               // 400000
    const int edge_blocks = (quads + 255) / 256;         // 1563
    edge_kernel<<<edge_blocks, 256>>>(ei, et, out);
}

// round 7
// speedup vs baseline: 1.1322x; 1.1322x over previous
#include <cuda_runtime.h>
#include <cstdint>

#define NUM_NODES 50000
#define INPUT_SIZE 128
#define NUM_REL 16
#define NUM_EDGES 1600000
#define CLAMP_MIN 1e-5f
#define CLAMP_MAX 0.99999f

// Node logit table: T[n][0:16] = x[n].W_src, T[n][16:32] = x[n].W_dst
__device__ float g_table[NUM_NODES * 32];

// ---------------------------------------------------------------------------
// Kernel A: 50000x128 @ 128x32 GEMM into g_table.  (Measured-best R3 config:
// 128 threads/block, tile 128 nodes x 32 cols, per thread 8 nodes x 4 cols.)
// ---------------------------------------------------------------------------
#define XPAD 132

__global__ void __launch_bounds__(128) node_logits_kernel(
    const float* __restrict__ x, const float* __restrict__ W)
{
    __shared__ float Ws[INPUT_SIZE][32];   // 16 KB [k][r]
    __shared__ float Xs[32][XPAD];         // 16.9 KB [k][node]

    const int tid = threadIdx.x;

    for (int idx = tid; idx < INPUT_SIZE * 32; idx += 128) {
        int k = idx >> 5;
        int r = idx & 31;
        Ws[k][r] = (r < NUM_REL) ? W[k * NUM_REL + r]
                                 : W[(k + INPUT_SIZE) * NUM_REL + (r - NUM_REL)];
    }

    const int node0 = blockIdx.x * 128;
    const int rg = tid & 7;    // 8 groups of 4 rel-cols
    const int ng = tid >> 3;   // 16 groups of 8 nodes

    float acc[8][4];
#pragma unroll
    for (int i = 0; i < 8; ++i)
#pragma unroll
        for (int j = 0; j < 4; ++j) acc[i][j] = 0.0f;

    for (int kc = 0; kc < 4; ++kc) {
        __syncthreads();
#pragma unroll
        for (int it = 0; it < 8; ++it) {
            int s = tid + it * 128;     // 0..1023
            int row = s >> 3;           // node within tile 0..127
            int c4  = s & 7;            // float4 within 32-float k-chunk
            int gr = node0 + row;
            if (gr >= NUM_NODES) gr = NUM_NODES - 1;   // dup loads OK
            float4 v = *reinterpret_cast<const float4*>(
                &x[(size_t)gr * INPUT_SIZE + kc * 32 + c4 * 4]);
            Xs[c4 * 4 + 0][row] = v.x;
            Xs[c4 * 4 + 1][row] = v.y;
            Xs[c4 * 4 + 2][row] = v.z;
            Xs[c4 * 4 + 3][row] = v.w;
        }
        __syncthreads();

#pragma unroll
        for (int kk = 0; kk < 32; ++kk) {
            int k = kc * 32 + kk;
            float4 wv = *reinterpret_cast<const float4*>(&Ws[k][rg * 4]);
            float4 xa = *reinterpret_cast<const float4*>(&Xs[kk][ng * 8]);
            float4 xb = *reinterpret_cast<const float4*>(&Xs[kk][ng * 8 + 4]);
            float xr[8] = {xa.x, xa.y, xa.z, xa.w, xb.x, xb.y, xb.z, xb.w};
#pragma unroll
            for (int i = 0; i < 8; ++i) {
                acc[i][0] += xr[i] * wv.x;
                acc[i][1] += xr[i] * wv.y;
                acc[i][2] += xr[i] * wv.z;
                acc[i][3] += xr[i] * wv.w;
            }
        }
    }

#pragma unroll
    for (int i = 0; i < 8; ++i) {
        int n = node0 + ng * 8 + i;
        if (n < NUM_NODES) {
            float4 o = make_float4(acc[i][0], acc[i][1], acc[i][2], acc[i][3]);
            *reinterpret_cast<float4*>(&g_table[(size_t)n * 32 + rg * 4]) = o;
        }
    }
}

// ---------------------------------------------------------------------------
// FMA/ALU-only clamped sigmoid (no MUFU; proven rel_err ~3e-7).
// ---------------------------------------------------------------------------
__device__ __forceinline__ float sigmoid_clamped(float v)
{
    v = fminf(fmaxf(v, -15.0f), 15.0f);
    float y = v * -1.4426950408889634f;
    float z = y + 12582912.0f;
    int   n = __float_as_int(z) - 0x4B400000;
    float f = y - (z - 12582912.0f);
    float p = 0.0013333558f;
    p = fmaf(p, f, 0.0096181291f);
    p = fmaf(p, f, 0.0555041086f);
    p = fmaf(p, f, 0.2402265069f);
    p = fmaf(p, f, 0.6931471806f);
    p = fmaf(p, f, 1.0f);
    float e = p * __int_as_float((n + 127) << 23);
    float d = 1.0f + e;
    float r = __int_as_float(0x7EF311C3 - __float_as_int(d));
    r = r * (2.0f - d * r);
    r = r * (2.0f - d * r);
    r = r * (2.0f - d * r);
    return fminf(fmaxf(r, CLAMP_MIN), CLAMP_MAX);
}

// ---------------------------------------------------------------------------
// Kernel B: 1 edge/thread. Index loads and output stores are perfectly
// coalesced (consecutive lanes -> consecutive addresses). Minimal per-block
// duration -> minimal launch-tail exposure; max occupancy.
// ---------------------------------------------------------------------------
__global__ void __launch_bounds__(256) edge_kernel(
    const int* __restrict__ ei,
    const int* __restrict__ et,
    float* __restrict__ out)
{
    const int e = blockIdx.x * 256 + threadIdx.x;
    if (e < NUM_EDGES) {
        int s = ei[e];
        int d = ei[NUM_EDGES + e];
        int t = et[e];
        float a = __ldg(&g_table[s * 32 + t]);
        float b = __ldg(&g_table[d * 32 + 16 + t]);
        out[e] = sigmoid_clamped(a + b);
    }
}

extern "C" void kernel_launch(void* const* d_in, const int* in_sizes, int n_in,
                              void* d_out, int out_size)
{
    const float* x  = (const float*)d_in[0];
    const float* W  = (const float*)d_in[1];
    const int*   ei = (const int*)d_in[2];
    const int*   et = (const int*)d_in[3];
    float* out = (float*)d_out;

    const int node_blocks = (NUM_NODES + 127) / 128;       // 391
    node_logits_kernel<<<node_blocks, 128>>>(x, W);

    const int edge_blocks = (NUM_EDGES + 255) / 256;       // 6250
    edge_kernel<<<edge_blocks, 256>>>(ei, et, out);
}

// round 9
// speedup vs baseline: 1.2804x; 1.1309x over previous
#include <cuda_runtime.h>
#include <cstdint>

#define NUM_NODES 50000
#define INPUT_SIZE 128
#define NUM_REL 16
#define NUM_EDGES 1600000
#define CLAMP_MIN 1e-5f
#define CLAMP_MAX 0.99999f

// Node logit table: T[n][0:16] = x[n].W_src, T[n][16:32] = x[n].W_dst
__device__ float g_table[NUM_NODES * 32];

// Packed f32x2 helpers (Blackwell FFMA2 — PTX-only).
__device__ __forceinline__ uint64_t pack2(float lo, float hi) {
    uint64_t r;
    asm("mov.b64 %0, {%1, %2};" : "=l"(r) : "f"(lo), "f"(hi));
    return r;
}
__device__ __forceinline__ void fma2(uint64_t& acc, uint64_t a, uint64_t b) {
    asm("fma.rn.f32x2 %0, %1, %2, %0;" : "+l"(acc) : "l"(a), "l"(b));
}
__device__ __forceinline__ float2 unpack2(uint64_t v) {
    float lo, hi;
    asm("mov.b64 {%0, %1}, %2;" : "=f"(lo), "=f"(hi) : "l"(v));
    return make_float2(lo, hi);
}

// ---------------------------------------------------------------------------
// Kernel A: 50000x128 @ 128x32 GEMM into g_table.
// 128 thr/block, 128-node tile, 8 nodes x 4 cols/thread as FFMA2 node-pairs.
// Double-buffered Xs with register-staged prefetch. XOR-swizzled Xs layout
// (node' = node ^ ((k>>2)<<2)): conflict-free stores AND reads, zero padding,
// so Ws(16K) + 2*Xs(16K each) = 48KB exactly (static smem cap).
// ---------------------------------------------------------------------------
__global__ void __launch_bounds__(128) node_logits_kernel(
    const float* __restrict__ x, const float* __restrict__ W)
{
    __shared__ float Ws[INPUT_SIZE][32];     // 16 KB [k][r]
    __shared__ float Xs[2][32][128];         // 32 KB [buf][k][node^swz]

    const int tid = threadIdx.x;

    for (int idx = tid; idx < INPUT_SIZE * 32; idx += 128) {
        int k = idx >> 5;
        int r = idx & 31;
        Ws[k][r] = (r < NUM_REL) ? W[k * NUM_REL + r]
                                 : W[(k + INPUT_SIZE) * NUM_REL + (r - NUM_REL)];
    }

    const int node0 = blockIdx.x * 128;
    const int rg = tid & 7;    // 8 groups of 4 rel-cols
    const int ng = tid >> 3;   // 16 groups of 8 nodes

    // Per-thread load coords (8 float4 per 32-k chunk)
    int lrow[8], lc4[8];
    const float* lp[8];
#pragma unroll
    for (int it = 0; it < 8; ++it) {
        int s = tid + it * 128;      // 0..1023
        lrow[it] = s >> 3;           // node within tile 0..127
        lc4[it]  = s & 7;            // float4 within 32-float k-chunk
        int gr = node0 + lrow[it];
        if (gr >= NUM_NODES) gr = NUM_NODES - 1;   // dup loads OK
        lp[it] = &x[(size_t)gr * INPUT_SIZE + lc4[it] * 4];
    }

    uint64_t acc2[4][4];             // [node-pair][col]
#pragma unroll
    for (int i = 0; i < 4; ++i)
#pragma unroll
        for (int j = 0; j < 4; ++j) acc2[i][j] = 0ull;

    // Prologue: load chunk 0, stage into buffer 0 (swizzled).
    float4 v[8];
#pragma unroll
    for (int it = 0; it < 8; ++it)
        v[it] = *reinterpret_cast<const float4*>(lp[it]);
#pragma unroll
    for (int it = 0; it < 8; ++it) {
        int sw = lrow[it] ^ (lc4[it] << 2);    // (k>>2)==c4 for all 4 components
        Xs[0][lc4[it] * 4 + 0][sw] = v[it].x;
        Xs[0][lc4[it] * 4 + 1][sw] = v[it].y;
        Xs[0][lc4[it] * 4 + 2][sw] = v[it].z;
        Xs[0][lc4[it] * 4 + 3][sw] = v[it].w;
    }
    __syncthreads();

#pragma unroll
    for (int kc = 0; kc < 4; ++kc) {
        const int buf = kc & 1;

        // Prefetch chunk kc+1 into registers.
        if (kc < 3) {
#pragma unroll
            for (int it = 0; it < 8; ++it)
                v[it] = *reinterpret_cast<const float4*>(lp[it] + (kc + 1) * 32);
        }

        // Compute on current buffer.
#pragma unroll
        for (int kk = 0; kk < 32; ++kk) {
            int k = kc * 32 + kk;
            const int swz = (kk >> 2) << 2;    // compile-time per unrolled kk
            float4 wv = *reinterpret_cast<const float4*>(&Ws[k][rg * 4]);
            uint64_t wd[4] = { pack2(wv.x, wv.x), pack2(wv.y, wv.y),
                               pack2(wv.z, wv.z), pack2(wv.w, wv.w) };
            float4 xa = *reinterpret_cast<const float4*>(&Xs[buf][kk][(ng * 8) ^ swz]);
            float4 xb = *reinterpret_cast<const float4*>(&Xs[buf][kk][(ng * 8 + 4) ^ swz]);
            uint64_t xp[4] = { pack2(xa.x, xa.y), pack2(xa.z, xa.w),
                               pack2(xb.x, xb.y), pack2(xb.z, xb.w) };
#pragma unroll
            for (int i = 0; i < 4; ++i)
#pragma unroll
                for (int j = 0; j < 4; ++j)
                    fma2(acc2[i][j], xp[i], wd[j]);
        }

        // Stage prefetched chunk into the other buffer (read-complete since
        // the sync at the end of the previous iteration).
        if (kc < 3) {
#pragma unroll
            for (int it = 0; it < 8; ++it) {
                int sw = lrow[it] ^ (lc4[it] << 2);
                Xs[buf ^ 1][lc4[it] * 4 + 0][sw] = v[it].x;
                Xs[buf ^ 1][lc4[it] * 4 + 1][sw] = v[it].y;
                Xs[buf ^ 1][lc4[it] * 4 + 2][sw] = v[it].z;
                Xs[buf ^ 1][lc4[it] * 4 + 3][sw] = v[it].w;
            }
            __syncthreads();
        }
    }

    // acc2[i][j]: nodes (ng*8+2i, ng*8+2i+1), col rg*4+j.
    // Swizzle note: xa/xb were loaded from swizzled addresses, but the pair
    // (lo,hi) of each xp is nodes (base^swz)+0,1 ... careful: the swizzle maps
    // blocks of 4 nodes; within a float4 the node order is preserved, and the
    // float4 at (ng*8)^swz holds nodes (ng*8)^swz .. +3. So the accumulator
    // actually corresponds to PERMUTED node ids n' = (ng*8 + pos) ^ swz ... 
    // BUT swz varies with kk, so each kk contributes to DIFFERENT nodes unless
    // the permutation is undone. It is undone: for fixed thread, the float4 we
    // read at (ng*8)^swz contains exactly nodes {(ng*8)^swz + 0..3}, which for
    // swz a multiple of 4 and ng*8 a multiple of 8 equals {ng*8 ^ swz + 0..3}
    // = nodes {ng*8+0..3} XOR swz — a DIFFERENT node set per kk. To keep the
    // node set fixed, the read must target nodes ng*8..ng*8+7: address =
    // (node) ^ swz. For a float4 starting at node ng*8: addresses
    // (ng*8+i)^swz = (ng*8)^swz + i (swz multiple of 4, i<4) — contiguous,
    // and they DO hold nodes ng*8+i (store wrote node `row` at row^swz).
    // So the loaded float4 is exactly nodes ng*8..ng*8+3. Correct as coded.
#pragma unroll
    for (int i = 0; i < 4; ++i) {
        float2 c0 = unpack2(acc2[i][0]);
        float2 c1 = unpack2(acc2[i][1]);
        float2 c2 = unpack2(acc2[i][2]);
        float2 c3 = unpack2(acc2[i][3]);
        int n0 = node0 + ng * 8 + 2 * i;
        if (n0 < NUM_NODES)
            *reinterpret_cast<float4*>(&g_table[(size_t)n0 * 32 + rg * 4]) =
                make_float4(c0.x, c1.x, c2.x, c3.x);
        if (n0 + 1 < NUM_NODES)
            *reinterpret_cast<float4*>(&g_table[(size_t)(n0 + 1) * 32 + rg * 4]) =
                make_float4(c0.y, c1.y, c2.y, c3.y);
    }
}

// ---------------------------------------------------------------------------
// FMA/ALU-only clamped sigmoid (no MUFU; proven rel_err ~3e-7).
// ---------------------------------------------------------------------------
__device__ __forceinline__ float sigmoid_clamped(float v)
{
    v = fminf(fmaxf(v, -15.0f), 15.0f);
    float y = v * -1.4426950408889634f;
    float z = y + 12582912.0f;
    int   n = __float_as_int(z) - 0x4B400000;
    float f = y - (z - 12582912.0f);
    float p = 0.0013333558f;
    p = fmaf(p, f, 0.0096181291f);
    p = fmaf(p, f, 0.0555041086f);
    p = fmaf(p, f, 0.2402265069f);
    p = fmaf(p, f, 0.6931471806f);
    p = fmaf(p, f, 1.0f);
    float e = p * __int_as_float((n + 127) << 23);
    float d = 1.0f + e;
    float r = __int_as_float(0x7EF311C3 - __float_as_int(d));
    r = r * (2.0f - d * r);
    r = r * (2.0f - d * r);
    r = r * (2.0f - d * r);
    return fminf(fmaxf(r, CLAMP_MIN), CLAMP_MAX);
}

// ---------------------------------------------------------------------------
// Kernel B: 1 edge/thread (measured-best; at the divergent-gather HW floor).
// ---------------------------------------------------------------------------
__global__ void __launch_bounds__(256) edge_kernel(
    const int* __restrict__ ei,
    const int* __restrict__ et,
    float* __restrict__ out)
{
    const int e = blockIdx.x * 256 + threadIdx.x;
    if (e < NUM_EDGES) {
        int s = ei[e];
        int d = ei[NUM_EDGES + e];
        int t = et[e];
        float a = __ldg(&g_table[s * 32 + t]);
        float b = __ldg(&g_table[d * 32 + 16 + t]);
        out[e] = sigmoid_clamped(a + b);
    }
}

extern "C" void kernel_launch(void* const* d_in, const int* in_sizes, int n_in,
                              void* d_out, int out_size)
{
    const float* x  = (const float*)d_in[0];
    const float* W  = (const float*)d_in[1];
    const int*   ei = (const int*)d_in[2];
    const int*   et = (const int*)d_in[3];
    float* out = (float*)d_out;

    const int node_blocks = (NUM_NODES + 127) / 128;       // 391
    node_logits_kernel<<<node_blocks, 128>>>(x, W);

    const int edge_blocks = (NUM_EDGES + 255) / 256;       // 6250
    edge_kernel<<<edge_blocks, 256>>>(ei, et, out);
}